// round 1
// baseline (speedup 1.0000x reference)
#include <cuda_runtime.h>
#include <math.h>

// ---------------- problem constants ----------------
constexpr int NB   = 8;        // batch
constexpr int LRAW = 131072;
constexpr int NL1  = 32768;    // after pool1
constexpr int NL2  = 8192;     // after pool2
constexpr int NS   = 2048;     // seq len
constexpr int ND   = 256;      // model dim
constexpr int NH   = 8;        // heads
constexpr int NDH  = 32;       // head dim
constexpr int NM   = 128;      // kernel-map dim
constexpr int NFF  = 1024;
constexpr int NBS  = NB * NS;  // 16384
constexpr int KV_SPLITS = 8;

// ---------------- device scratch (no allocs allowed) ----------------
__device__ float g_h1 [NB * NL1 * 8];
__device__ float g_h2 [NB * NL2 * 16];
__device__ float g_ain[NBS * ND];
__device__ float g_q  [NBS * ND];
__device__ float g_k  [NBS * ND];
__device__ float g_v  [NBS * ND];
__device__ float g_qt [(size_t)NBS * NH * NM];
__device__ float g_kt [(size_t)NBS * NH * NM];
__device__ float g_kv [NB * NH * NM * NDH];
__device__ float g_kvp[KV_SPLITS * NB * NH * NM * NDH];
__device__ float g_o  [NBS * ND];
__device__ float g_mid[(size_t)NBS * NFF];

// ---------------- conv stem ----------------
// conv1: x[B,131072,1] -> conv(k=11,SAME) -> relu -> pool4 -> h1[B,32768,8]
__global__ void conv1_pool(const float* __restrict__ x, const float* __restrict__ w,
                           const float* __restrict__ bias, float* __restrict__ out) {
    __shared__ float ws[88];
    __shared__ float bsm[8];
    if (threadIdx.x < 88) ws[threadIdx.x] = w[threadIdx.x];
    if (threadIdx.x < 8)  bsm[threadIdx.x] = bias[threadIdx.x];
    __syncthreads();
    int idx = blockIdx.x * blockDim.x + threadIdx.x;
    if (idx >= NB * NL1) return;
    int b = idx >> 15, lo = idx & (NL1 - 1);
    const float* xb = x + (size_t)b * LRAW;
    float acc[8] = {0.f,0.f,0.f,0.f,0.f,0.f,0.f,0.f};
#pragma unroll
    for (int p = 0; p < 4; p++) {
        int l = 4 * lo + p;
        float conv[8];
#pragma unroll
        for (int c = 0; c < 8; c++) conv[c] = bsm[c];
#pragma unroll
        for (int j = 0; j < 11; j++) {
            int li = l + j - 5;
            float xv = (li >= 0 && li < LRAW) ? __ldg(&xb[li]) : 0.f;
#pragma unroll
            for (int c = 0; c < 8; c++) conv[c] += xv * ws[j * 8 + c];
        }
#pragma unroll
        for (int c = 0; c < 8; c++) acc[c] += fmaxf(conv[c], 0.f);
    }
#pragma unroll
    for (int c = 0; c < 8; c++) out[(size_t)idx * 8 + c] = acc[c] * 0.25f;
}

// conv2: h1[B,32768,8] -> conv(k=3) -> relu -> pool4 -> h2[B,8192,16]
__global__ void conv2_pool(const float* __restrict__ in, const float* __restrict__ w,
                           const float* __restrict__ bias, float* __restrict__ out) {
    __shared__ float ws[384];
    __shared__ float bsm[16];
    for (int i = threadIdx.x; i < 384; i += blockDim.x) ws[i] = w[i];
    if (threadIdx.x < 16) bsm[threadIdx.x] = bias[threadIdx.x];
    __syncthreads();
    int idx = blockIdx.x * blockDim.x + threadIdx.x;
    if (idx >= NB * NL2) return;
    int b = idx >> 13, lo = idx & (NL2 - 1);
    float acc[16];
#pragma unroll
    for (int c = 0; c < 16; c++) acc[c] = 0.f;
#pragma unroll
    for (int p = 0; p < 4; p++) {
        int l = 4 * lo + p;
        float conv[16];
#pragma unroll
        for (int c = 0; c < 16; c++) conv[c] = bsm[c];
#pragma unroll
        for (int j = 0; j < 3; j++) {
            int li = l + j - 1;
            if (li >= 0 && li < NL1) {
                const float* row = in + ((size_t)b * NL1 + li) * 8;
#pragma unroll
                for (int ci = 0; ci < 8; ci++) {
                    float xv = __ldg(&row[ci]);
#pragma unroll
                    for (int co = 0; co < 16; co++) conv[co] += xv * ws[(j * 8 + ci) * 16 + co];
                }
            }
        }
#pragma unroll
        for (int c = 0; c < 16; c++) acc[c] += fmaxf(conv[c], 0.f);
    }
#pragma unroll
    for (int c = 0; c < 16; c++) out[(size_t)idx * 16 + c] = acc[c] * 0.25f;
}

// conv3: h2[B,8192,16] -> conv(k=3) -> relu -> pool4 -> out[B,2048,256]
// one block per (b,lo); thread = output channel; weights register-cached.
__global__ void conv3_pool(const float* __restrict__ in, const float* __restrict__ w,
                           const float* __restrict__ bias, float* __restrict__ out) {
    int blk = blockIdx.x;
    int b = blk >> 11, lo = blk & (NS - 1);
    int co = threadIdx.x;
    __shared__ float insm[6 * 16];
    if (threadIdx.x < 96) {
        int rr = threadIdx.x >> 4, ci = threadIdx.x & 15;
        int li = 4 * lo - 1 + rr;
        insm[threadIdx.x] = (li >= 0 && li < NL2) ? in[((size_t)b * NL2 + li) * 16 + ci] : 0.f;
    }
    float wreg[48];
#pragma unroll
    for (int i = 0; i < 48; i++) wreg[i] = __ldg(&w[(size_t)i * ND + co]);
    float bv = __ldg(&bias[co]);
    __syncthreads();
    float acc = 0.f;
#pragma unroll
    for (int p = 0; p < 4; p++) {
        float conv = bv;
#pragma unroll
        for (int j = 0; j < 3; j++) {
#pragma unroll
            for (int ci = 0; ci < 16; ci++)
                conv += insm[(p + j) * 16 + ci] * wreg[j * 16 + ci];
        }
        acc += fmaxf(conv, 0.f);
    }
    out[((size_t)b * NS + lo) * ND + co] = acc * 0.25f;
}

// ---------------- LayerCentering: dst = src - mean(src, axis=-1) ----------------
__global__ void lc_kernel(const float* __restrict__ src, float* __restrict__ dst) {
    int row = blockIdx.x;
    int tid = threadIdx.x;
    float v = src[(size_t)row * ND + tid];
    float s = v;
#pragma unroll
    for (int off = 16; off; off >>= 1) s += __shfl_down_sync(0xffffffffu, s, off);
    __shared__ float red[8];
    __shared__ float meansh;
    if ((tid & 31) == 0) red[tid >> 5] = s;
    __syncthreads();
    if (tid == 0) {
        float t = 0.f;
#pragma unroll
        for (int i = 0; i < 8; i++) t += red[i];
        meansh = t * (1.0f / ND);
    }
    __syncthreads();
    dst[(size_t)row * ND + tid] = v - meansh;
}

// ---------------- generic tiled fp32 GEMM: C = A[M,K] @ W[K,N] + bias (+relu/+add) ----------------
template <bool RELU, bool ADD>
__global__ void gemm_kernel(const float* __restrict__ A, const float* __restrict__ W,
                            const float* __restrict__ bias, const float* __restrict__ Cin,
                            float* __restrict__ C, int Mdim, int Ndim, int Kdim) {
    __shared__ float As[16 * 68];   // [k][m], padded
    __shared__ float Bs[16 * 64];   // [k][n]
    const int tid = threadIdx.x;
    const int tx = tid & 15, ty = tid >> 4;
    const int m0 = blockIdx.y * 64, n0 = blockIdx.x * 64;
    float acc[4][4];
#pragma unroll
    for (int i = 0; i < 4; i++)
#pragma unroll
        for (int j = 0; j < 4; j++) acc[i][j] = 0.f;

    for (int k0 = 0; k0 < Kdim; k0 += 16) {
        {
            int c = tid & 15, r0 = tid >> 4;
#pragma unroll
            for (int i = 0; i < 4; i++) {
                int r = r0 + i * 16;
                As[c * 68 + r] = A[(size_t)(m0 + r) * Kdim + k0 + c];
            }
        }
        {
            int n = tid & 63, kk0 = tid >> 6;
#pragma unroll
            for (int i = 0; i < 4; i++) {
                int kk = kk0 + i * 4;
                Bs[kk * 64 + n] = W[(size_t)(k0 + kk) * Ndim + n0 + n];
            }
        }
        __syncthreads();
#pragma unroll
        for (int kk = 0; kk < 16; kk++) {
            float4 av = *(const float4*)&As[kk * 68 + ty * 4];
            float4 bv = *(const float4*)&Bs[kk * 64 + tx * 4];
            acc[0][0] += av.x * bv.x; acc[0][1] += av.x * bv.y; acc[0][2] += av.x * bv.z; acc[0][3] += av.x * bv.w;
            acc[1][0] += av.y * bv.x; acc[1][1] += av.y * bv.y; acc[1][2] += av.y * bv.z; acc[1][3] += av.y * bv.w;
            acc[2][0] += av.z * bv.x; acc[2][1] += av.z * bv.y; acc[2][2] += av.z * bv.z; acc[2][3] += av.z * bv.w;
            acc[3][0] += av.w * bv.x; acc[3][1] += av.w * bv.y; acc[3][2] += av.w * bv.z; acc[3][3] += av.w * bv.w;
        }
        __syncthreads();
    }
#pragma unroll
    for (int i = 0; i < 4; i++) {
        int row = m0 + ty * 4 + i;
#pragma unroll
        for (int j = 0; j < 4; j++) {
            int col = n0 + tx * 4 + j;
            float val = acc[i][j] + __ldg(&bias[col]);
            if (RELU) val = fmaxf(val, 0.f);
            if (ADD)  val += Cin[(size_t)row * Ndim + col];
            C[(size_t)row * Ndim + col] = val;
        }
    }
}

// ---------------- fourier features + exponential positional modulation ----------------
// q,k: [BS, 256] -> qt,kt: [BS, H, 128]
__global__ void fourier_kernel(const float* __restrict__ q, const float* __restrict__ k,
                               const float* __restrict__ omega, const float* __restrict__ gamma,
                               float* __restrict__ qt, float* __restrict__ kt) {
    int bs = blockIdx.x;
    int tid = threadIdx.x;
    __shared__ float qrow[ND], krow[ND];
    qrow[tid] = q[(size_t)bs * ND + tid];
    krow[tid] = k[(size_t)bs * ND + tid];
    __syncthreads();
    int h = tid >> 5, lane = tid & 31;
    const float* om = omega + h * NDH * (NM / 2);
    float pq0 = 0.f, pq1 = 0.f, pk0 = 0.f, pk1 = 0.f;
#pragma unroll 8
    for (int d = 0; d < NDH; d++) {
        float qd = qrow[h * NDH + d], kd = krow[h * NDH + d];
        float o0 = __ldg(&om[d * 64 + lane]);
        float o1 = __ldg(&om[d * 64 + lane + 32]);
        pq0 += qd * o0; pq1 += qd * o1;
        pk0 += kd * o0; pk1 += kd * o1;
    }
    int s = bs & (NS - 1);
    float t = s * (1.0f / (NS - 1));
    float g = __ldg(&gamma[h]);
    float sl0 = 2.0f - lane * (1.0f / 32.0f);
    float sl1 = 2.0f - (lane + 32) * (1.0f / 32.0f);
    const float invs = 0.08838834764831845f;   // 1/sqrt(128)
    float a0 = g * t * sl0, a1 = g * t * sl1;
    float b0 = g * (1.0f - t) * sl0, b1 = g * (1.0f - t) * sl1;
    size_t base = ((size_t)bs * NH + h) * NM;
    qt[base + lane]      = cosf(pq0) * invs * expf(a0);
    qt[base + lane + 32] = cosf(pq1) * invs * expf(a1);
    qt[base + lane + 64] = sinf(pq0) * invs * expf(b0);
    qt[base + lane + 96] = sinf(pq1) * invs * expf(b1);
    kt[base + lane]      = cosf(pk0) * invs * expf(-a0);
    kt[base + lane + 32] = cosf(pk1) * invs * expf(-a1);
    kt[base + lane + 64] = sinf(pk0) * invs * expf(-b0);
    kt[base + lane + 96] = sinf(pk1) * invs * expf(-b1);
}

// ---------------- kv = sum_s kt[b,s,h,:]^T v[b,s,h,:]  (split over S, deterministic) ----------------
__global__ void kv_partial(const float* __restrict__ kt, const float* __restrict__ v,
                           float* __restrict__ kvp) {
    int bh = blockIdx.x;               // b*8+h
    int b = bh >> 3, h = bh & 7;
    int chunk = blockIdx.y;            // 0..7, 256 s each
    int m = threadIdx.x;               // 0..127
    __shared__ float vs[64 * 32];
    float acc[32];
#pragma unroll
    for (int e = 0; e < 32; e++) acc[e] = 0.f;
    int sbase = chunk * (NS / KV_SPLITS);
    for (int s0 = sbase; s0 < sbase + NS / KV_SPLITS; s0 += 64) {
        __syncthreads();
        for (int idx = threadIdx.x; idx < 64 * 32; idx += 128) {
            int i = idx >> 5, e = idx & 31;
            vs[idx] = v[((size_t)(b * NS + s0 + i)) * ND + h * NDH + e];
        }
        __syncthreads();
#pragma unroll 4
        for (int i = 0; i < 64; i++) {
            float kval = kt[(((size_t)(b * NS + s0 + i)) * NH + h) * NM + m];
#pragma unroll
            for (int e = 0; e < 32; e++) acc[e] += kval * vs[i * 32 + e];
        }
    }
    float* dst = kvp + (((size_t)chunk * (NB * NH) + bh) * NM + m) * NDH;
#pragma unroll
    for (int e = 0; e < 32; e++) dst[e] = acc[e];
}

__global__ void kv_reduce(const float* __restrict__ kvp, float* __restrict__ kv) {
    int idx = blockIdx.x * blockDim.x + threadIdx.x;
    if (idx >= NB * NH * NM * NDH) return;
    float s = 0.f;
#pragma unroll
    for (int c = 0; c < KV_SPLITS; c++) s += kvp[(size_t)c * (NB * NH * NM * NDH) + idx];
    kv[idx] = s;
}

// ---------------- o[b,s,h,:] = qt[b,s,h,:] @ kv[b,h,:,:] ----------------
__global__ void attn_o(const float* __restrict__ qt, const float* __restrict__ kv,
                       float* __restrict__ o) {
    int bh = blockIdx.x;
    int b = bh >> 3, h = bh & 7;
    int s0 = blockIdx.y * 32;
    __shared__ float kvs[NM * NDH];    // 16KB
    __shared__ float qsm[32 * NM];     // 16KB
    for (int idx = threadIdx.x; idx < NM * NDH; idx += 256)
        kvs[idx] = kv[(size_t)bh * (NM * NDH) + idx];
    for (int idx = threadIdx.x; idx < 32 * NM; idx += 256) {
        int si = idx >> 7, m = idx & 127;
        qsm[idx] = qt[(((size_t)(b * NS + s0 + si)) * NH + h) * NM + m];
    }
    __syncthreads();
    int e = threadIdx.x & 31, sg = threadIdx.x >> 5;   // sg 0..7
    float acc[4] = {0.f, 0.f, 0.f, 0.f};
#pragma unroll 4
    for (int m = 0; m < NM; m++) {
        float kval = kvs[m * 32 + e];
#pragma unroll
        for (int i = 0; i < 4; i++) acc[i] += qsm[(sg * 4 + i) * NM + m] * kval;
    }
#pragma unroll
    for (int i = 0; i < 4; i++)
        o[((size_t)(b * NS + s0 + sg * 4 + i)) * ND + h * NDH + e] = acc[i];
}

// ---------------- host launcher ----------------
extern "C" void kernel_launch(void* const* d_in, const int* in_sizes, int n_in,
                              void* d_out, int out_size) {
    const float* x     = (const float*)d_in[0];
    const float* cw0   = (const float*)d_in[1];
    const float* cb0   = (const float*)d_in[2];
    const float* cw1   = (const float*)d_in[3];
    const float* cb1   = (const float*)d_in[4];
    const float* cw2   = (const float*)d_in[5];
    const float* cb2   = (const float*)d_in[6];
    const float* Wq    = (const float*)d_in[7];
    const float* bq    = (const float*)d_in[8];
    const float* Wk    = (const float*)d_in[9];
    const float* bk    = (const float*)d_in[10];
    const float* Wv    = (const float*)d_in[11];
    const float* bv    = (const float*)d_in[12];
    const float* Wo    = (const float*)d_in[13];
    const float* bo    = (const float*)d_in[14];
    const float* omega = (const float*)d_in[15];
    const float* gamma = (const float*)d_in[16];
    const float* W1    = (const float*)d_in[17];
    const float* b1    = (const float*)d_in[18];
    const float* W2    = (const float*)d_in[19];
    const float* b2    = (const float*)d_in[20];
    float* hout = (float*)d_out;

    float *p_h1, *p_h2, *p_ain, *p_q, *p_k, *p_v, *p_qt, *p_kt, *p_kv, *p_kvp, *p_o, *p_mid;
    cudaGetSymbolAddress((void**)&p_h1,  g_h1);
    cudaGetSymbolAddress((void**)&p_h2,  g_h2);
    cudaGetSymbolAddress((void**)&p_ain, g_ain);
    cudaGetSymbolAddress((void**)&p_q,   g_q);
    cudaGetSymbolAddress((void**)&p_k,   g_k);
    cudaGetSymbolAddress((void**)&p_v,   g_v);
    cudaGetSymbolAddress((void**)&p_qt,  g_qt);
    cudaGetSymbolAddress((void**)&p_kt,  g_kt);
    cudaGetSymbolAddress((void**)&p_kv,  g_kv);
    cudaGetSymbolAddress((void**)&p_kvp, g_kvp);
    cudaGetSymbolAddress((void**)&p_o,   g_o);
    cudaGetSymbolAddress((void**)&p_mid, g_mid);

    // conv stem
    conv1_pool<<<(NB * NL1 + 255) / 256, 256>>>(x, cw0, cb0, p_h1);
    conv2_pool<<<(NB * NL2 + 255) / 256, 256>>>(p_h1, cw1, cb1, p_h2);
    conv3_pool<<<NB * NS, 256>>>(p_h2, cw2, cb2, hout);

    for (int l = 0; l < 2; l++) {
        const float* Wq_l = Wq + (size_t)l * ND * ND;
        const float* Wk_l = Wk + (size_t)l * ND * ND;
        const float* Wv_l = Wv + (size_t)l * ND * ND;
        const float* Wo_l = Wo + (size_t)l * ND * ND;
        const float* W1_l = W1 + (size_t)l * ND * NFF;
        const float* W2_l = W2 + (size_t)l * NFF * ND;
        const float* om_l = omega + (size_t)l * NH * NDH * (NM / 2);
        const float* g_l  = gamma + (size_t)l * NH;

        lc_kernel<<<NBS, ND>>>(hout, p_ain);

        dim3 gN256(ND / 64, NBS / 64);
        gemm_kernel<false, false><<<gN256, 256>>>(p_ain, Wq_l, bq + l * ND, nullptr, p_q, NBS, ND, ND);
        gemm_kernel<false, false><<<gN256, 256>>>(p_ain, Wk_l, bk + l * ND, nullptr, p_k, NBS, ND, ND);
        gemm_kernel<false, false><<<gN256, 256>>>(p_ain, Wv_l, bv + l * ND, nullptr, p_v, NBS, ND, ND);

        fourier_kernel<<<NBS, 256>>>(p_q, p_k, om_l, g_l, p_qt, p_kt);

        kv_partial<<<dim3(NB * NH, KV_SPLITS), 128>>>(p_kt, p_v, p_kvp);
        kv_reduce<<<(NB * NH * NM * NDH + 255) / 256, 256>>>(p_kvp, p_kv);

        attn_o<<<dim3(NB * NH, NS / 32), 256>>>(p_qt, p_kv, p_o);

        gemm_kernel<false, true><<<gN256, 256>>>(p_o, Wo_l, bo + l * ND, hout, hout, NBS, ND, ND);

        lc_kernel<<<NBS, ND>>>(hout, p_ain);

        dim3 gN1024(NFF / 64, NBS / 64);
        gemm_kernel<true, false><<<gN1024, 256>>>(p_ain, W1_l, b1 + l * NFF, nullptr, p_mid, NBS, NFF, ND);
        gemm_kernel<false, true><<<gN256, 256>>>(p_mid, W2_l, b2 + l * ND, hout, hout, NBS, ND, NFF);
    }
}

// round 5
// speedup vs baseline: 1.2048x; 1.2048x over previous
#include <cuda_runtime.h>
#include <math.h>
#include <stdint.h>

// ---------------- problem constants ----------------
constexpr int NB   = 8;        // batch
constexpr int LRAW = 131072;
constexpr int NL1  = 32768;    // after pool1
constexpr int NL2  = 8192;     // after pool2
constexpr int NS   = 2048;     // seq len
constexpr int ND   = 256;      // model dim
constexpr int NH   = 8;        // heads
constexpr int NDH  = 32;       // head dim
constexpr int NM   = 128;      // kernel-map dim
constexpr int NFF  = 1024;
constexpr int NBS  = NB * NS;  // 16384
constexpr int KV_SPLITS = 8;

// ---------------- device scratch (no allocs allowed) ----------------
__device__ float g_h1 [NB * NL1 * 8];
__device__ float g_h2 [NB * NL2 * 16];
__device__ float g_ain[NBS * ND];
__device__ float g_q  [NBS * ND];
__device__ float g_k  [NBS * ND];
__device__ float g_v  [NBS * ND];
__device__ float g_qt [(size_t)NBS * NH * NM];
__device__ float g_kt [(size_t)NBS * NH * NM];
__device__ float g_kv [NB * NH * NM * NDH];
__device__ float g_kvp[KV_SPLITS * NB * NH * NM * NDH];
__device__ float g_o  [NBS * ND];
__device__ float g_mid[(size_t)NBS * NFF];

// ---------------- helpers ----------------
__device__ __forceinline__ uint32_t smem_u32(const void* p) {
    uint32_t a;
    asm("{ .reg .u64 t; cvta.to.shared.u64 t, %1; cvt.u32.u64 %0, t; }" : "=r"(a) : "l"(p));
    return a;
}
__device__ __forceinline__ uint64_t dup_f32(float x) {
    uint64_t r;
    asm("mov.b64 %0, {%1, %1};" : "=l"(r) : "f"(x));
    return r;
}
__device__ __forceinline__ void ffma2(uint64_t& c, uint64_t a, uint64_t b) {
    asm("fma.rn.f32x2 %0, %1, %2, %0;" : "+l"(c) : "l"(a), "l"(b));
}
__device__ __forceinline__ float2 unpack2(uint64_t v) {
    float lo, hi;
    asm("mov.b64 {%0, %1}, %2;" : "=f"(lo), "=f"(hi) : "l"(v));
    return make_float2(lo, hi);
}
#define CP_ASYNC16(dst, src) \
    asm volatile("cp.async.cg.shared.global [%0], [%1], 16;" :: "r"(dst), "l"(src))
#define CP_COMMIT() asm volatile("cp.async.commit_group;" ::: "memory")
#define CP_WAIT0()  asm volatile("cp.async.wait_group 0;" ::: "memory")

// ---------------- FFMA2 GEMM: C = A[M,K] @ W[K,N] + bias (+relu/+add) ----------------
// CTA 128x128, 256 threads (8 warps). Warp w covers n-cols [w*16, w*16+16) (warp-uniform
// B loads -> pure smem broadcast). Thread (ty=lane) covers rows ty*4..ty*4+3.
// K chunks of 16. A transposed to smem [k][m] (stride 132, LDS.128 fragments conflict-free).
// B via cp.async [k][n] (stride 128). Inner: 32 packed fp32x2 FMAs per k.
constexpr int GK   = 16;
constexpr int GAS  = 132;               // As row stride (floats)
constexpr int GBS  = 128;               // Bs row stride (floats)
constexpr int GA_F = GK * GAS;          // 2112
constexpr int GB_F = GK * GBS;          // 2048
constexpr int GT_SMEM = (2 * GA_F + 2 * GB_F) * 4;  // 33280 B

template <bool RELU, bool ADD>
__global__ void __launch_bounds__(256, 2) gemm_ffma2(
        const float* __restrict__ A, const float* __restrict__ W,
        const float* __restrict__ bias, const float* __restrict__ Cin,
        float* __restrict__ C, int Ndim, int Kdim) {
    extern __shared__ float sm[];
    const uint32_t sbase = smem_u32(sm);
    const int tid = threadIdx.x;
    const int tx = tid >> 5;            // warp id: n-slice
    const int ty = tid & 31;            // lane: m rows ty*4..ty*4+3
    const int m0 = blockIdx.y * 128, n0 = blockIdx.x * 128;
    const int nch = Kdim / GK;

    uint64_t acc[4][8];
#pragma unroll
    for (int i = 0; i < 4; i++)
#pragma unroll
        for (int j = 0; j < 8; j++) acc[i][j] = 0ull;

    // A staging: 512 float4 per chunk (128 rows x 4), 2 per thread
    const int ar0 = tid >> 2, ac4 = tid & 3;
    float4 aReg0, aReg1;

    auto ldgA = [&](int c) {
        aReg0 = *(const float4*)(A + (size_t)(m0 + ar0) * Kdim + c * GK + ac4 * 4);
        aReg1 = *(const float4*)(A + (size_t)(m0 + ar0 + 64) * Kdim + c * GK + ac4 * 4);
    };
    auto stsA = [&](int buf) {
        float* As = sm + buf * GA_F;
        const float a0[4] = {aReg0.x, aReg0.y, aReg0.z, aReg0.w};
        const float a1[4] = {aReg1.x, aReg1.y, aReg1.z, aReg1.w};
#pragma unroll
        for (int j = 0; j < 4; j++) {
            As[(ac4 * 4 + j) * GAS + ar0]      = a0[j];
            As[(ac4 * 4 + j) * GAS + ar0 + 64] = a1[j];
        }
    };
    auto cpB = [&](int c, int buf) {
        const float* Wp = W + (size_t)(c * GK) * Ndim + n0;
        uint32_t bb = sbase + (2 * GA_F + buf * GB_F) * 4;
#pragma unroll
        for (int i = 0; i < 2; i++) {
            int idx = tid + i * 256;
            int row = idx >> 5, col4 = idx & 31;
            CP_ASYNC16(bb + (row * GBS + col4 * 4) * 4,
                       Wp + (size_t)row * Ndim + col4 * 4);
        }
        CP_COMMIT();
    };
    auto compute = [&](int buf) {
        const float* As = sm + buf * GA_F;
        const float* Bs = sm + 2 * GA_F + buf * GB_F;
#pragma unroll
        for (int k = 0; k < GK; k++) {
            float4 av = *(const float4*)(As + k * GAS + ty * 4);
            uint64_t ad[4];
            ad[0] = dup_f32(av.x); ad[1] = dup_f32(av.y);
            ad[2] = dup_f32(av.z); ad[3] = dup_f32(av.w);
            const uint64_t* bp = (const uint64_t*)(Bs + k * GBS + tx * 16);
            uint64_t bv[8];
#pragma unroll
            for (int j = 0; j < 8; j++) bv[j] = bp[j];
#pragma unroll
            for (int i = 0; i < 4; i++)
#pragma unroll
                for (int j = 0; j < 8; j++) ffma2(acc[i][j], ad[i], bv[j]);
        }
    };

    ldgA(0); cpB(0, 0);
    stsA(0); CP_WAIT0(); __syncthreads();

    for (int c = 0; c < nch; c++) {
        const int buf = c & 1;
        if (c + 1 < nch) { ldgA(c + 1); cpB(c + 1, buf ^ 1); }
        compute(buf);
        if (c + 1 < nch) {
            CP_WAIT0();
            __syncthreads();
            stsA(buf ^ 1);
            __syncthreads();
        }
    }

    // epilogue: rows m0+ty*4+i, cols n0+tx*16+2j
    const int colb = n0 + tx * 16;
    float bs[16];
#pragma unroll
    for (int j = 0; j < 16; j++) bs[j] = __ldg(&bias[colb + j]);
#pragma unroll
    for (int i = 0; i < 4; i++) {
        const int row = m0 + ty * 4 + i;
        float* cp = C + (size_t)row * Ndim + colb;
        const float* cin = Cin + (size_t)row * Ndim + colb;
#pragma unroll
        for (int j = 0; j < 8; j++) {
            float2 v = unpack2(acc[i][j]);
            v.x += bs[2 * j]; v.y += bs[2 * j + 1];
            if (RELU) { v.x = fmaxf(v.x, 0.f); v.y = fmaxf(v.y, 0.f); }
            if (ADD)  { float2 ci = *(const float2*)(cin + 2 * j); v.x += ci.x; v.y += ci.y; }
            *(float2*)(cp + 2 * j) = v;
        }
    }
}

// ---------------- conv stem ----------------
__global__ void conv1_pool(const float* __restrict__ x, const float* __restrict__ w,
                           const float* __restrict__ bias, float* __restrict__ out) {
    __shared__ float ws[88];
    __shared__ float bsm[8];
    if (threadIdx.x < 88) ws[threadIdx.x] = w[threadIdx.x];
    if (threadIdx.x < 8)  bsm[threadIdx.x] = bias[threadIdx.x];
    __syncthreads();
    int idx = blockIdx.x * blockDim.x + threadIdx.x;
    if (idx >= NB * NL1) return;
    int b = idx >> 15, lo = idx & (NL1 - 1);
    const float* xb = x + (size_t)b * LRAW;
    float acc[8] = {0.f,0.f,0.f,0.f,0.f,0.f,0.f,0.f};
#pragma unroll
    for (int p = 0; p < 4; p++) {
        int l = 4 * lo + p;
        float conv[8];
#pragma unroll
        for (int c = 0; c < 8; c++) conv[c] = bsm[c];
#pragma unroll
        for (int j = 0; j < 11; j++) {
            int li = l + j - 5;
            float xv = (li >= 0 && li < LRAW) ? __ldg(&xb[li]) : 0.f;
#pragma unroll
            for (int c = 0; c < 8; c++) conv[c] += xv * ws[j * 8 + c];
        }
#pragma unroll
        for (int c = 0; c < 8; c++) acc[c] += fmaxf(conv[c], 0.f);
    }
#pragma unroll
    for (int c = 0; c < 8; c++) out[(size_t)idx * 8 + c] = acc[c] * 0.25f;
}

__global__ void conv2_pool(const float* __restrict__ in, const float* __restrict__ w,
                           const float* __restrict__ bias, float* __restrict__ out) {
    __shared__ float ws[384];
    __shared__ float bsm[16];
    for (int i = threadIdx.x; i < 384; i += blockDim.x) ws[i] = w[i];
    if (threadIdx.x < 16) bsm[threadIdx.x] = bias[threadIdx.x];
    __syncthreads();
    int idx = blockIdx.x * blockDim.x + threadIdx.x;
    if (idx >= NB * NL2) return;
    int b = idx >> 13, lo = idx & (NL2 - 1);
    float acc[16];
#pragma unroll
    for (int c = 0; c < 16; c++) acc[c] = 0.f;
#pragma unroll
    for (int p = 0; p < 4; p++) {
        int l = 4 * lo + p;
        float conv[16];
#pragma unroll
        for (int c = 0; c < 16; c++) conv[c] = bsm[c];
#pragma unroll
        for (int j = 0; j < 3; j++) {
            int li = l + j - 1;
            if (li >= 0 && li < NL1) {
                const float* row = in + ((size_t)b * NL1 + li) * 8;
#pragma unroll
                for (int ci = 0; ci < 8; ci++) {
                    float xv = __ldg(&row[ci]);
#pragma unroll
                    for (int co = 0; co < 16; co++) conv[co] += xv * ws[(j * 8 + ci) * 16 + co];
                }
            }
        }
#pragma unroll
        for (int c = 0; c < 16; c++) acc[c] += fmaxf(conv[c], 0.f);
    }
#pragma unroll
    for (int c = 0; c < 16; c++) out[(size_t)idx * 16 + c] = acc[c] * 0.25f;
}

__global__ void conv3_pool(const float* __restrict__ in, const float* __restrict__ w,
                           const float* __restrict__ bias, float* __restrict__ out) {
    int blk = blockIdx.x;
    int b = blk >> 11, lo = blk & (NS - 1);
    int co = threadIdx.x;
    __shared__ float insm[6 * 16];
    if (threadIdx.x < 96) {
        int rr = threadIdx.x >> 4, ci = threadIdx.x & 15;
        int li = 4 * lo - 1 + rr;
        insm[threadIdx.x] = (li >= 0 && li < NL2) ? in[((size_t)b * NL2 + li) * 16 + ci] : 0.f;
    }
    float wreg[48];
#pragma unroll
    for (int i = 0; i < 48; i++) wreg[i] = __ldg(&w[(size_t)i * ND + co]);
    float bv = __ldg(&bias[co]);
    __syncthreads();
    float acc = 0.f;
#pragma unroll
    for (int p = 0; p < 4; p++) {
        float conv = bv;
#pragma unroll
        for (int j = 0; j < 3; j++) {
#pragma unroll
            for (int ci = 0; ci < 16; ci++)
                conv += insm[(p + j) * 16 + ci] * wreg[j * 16 + ci];
        }
        acc += fmaxf(conv, 0.f);
    }
    out[((size_t)b * NS + lo) * ND + co] = acc * 0.25f;
}

// ---------------- LayerCentering ----------------
__global__ void lc_kernel(const float* __restrict__ src, float* __restrict__ dst) {
    int row = blockIdx.x;
    int tid = threadIdx.x;
    float v = src[(size_t)row * ND + tid];
    float s = v;
#pragma unroll
    for (int off = 16; off; off >>= 1) s += __shfl_down_sync(0xffffffffu, s, off);
    __shared__ float red[8];
    __shared__ float meansh;
    if ((tid & 31) == 0) red[tid >> 5] = s;
    __syncthreads();
    if (tid == 0) {
        float t = 0.f;
#pragma unroll
        for (int i = 0; i < 8; i++) t += red[i];
        meansh = t * (1.0f / ND);
    }
    __syncthreads();
    dst[(size_t)row * ND + tid] = v - meansh;
}

// ---------------- fourier features + exponential positional modulation ----------------
__global__ void fourier_kernel(const float* __restrict__ q, const float* __restrict__ k,
                               const float* __restrict__ omega, const float* __restrict__ gamma,
                               float* __restrict__ qt, float* __restrict__ kt) {
    int bs = blockIdx.x;
    int tid = threadIdx.x;
    __shared__ float qrow[ND], krow[ND];
    qrow[tid] = q[(size_t)bs * ND + tid];
    krow[tid] = k[(size_t)bs * ND + tid];
    __syncthreads();
    int h = tid >> 5, lane = tid & 31;
    const float* om = omega + h * NDH * (NM / 2);
    float pq0 = 0.f, pq1 = 0.f, pk0 = 0.f, pk1 = 0.f;
#pragma unroll 8
    for (int d = 0; d < NDH; d++) {
        float qd = qrow[h * NDH + d], kd = krow[h * NDH + d];
        float o0 = __ldg(&om[d * 64 + lane]);
        float o1 = __ldg(&om[d * 64 + lane + 32]);
        pq0 += qd * o0; pq1 += qd * o1;
        pk0 += kd * o0; pk1 += kd * o1;
    }
    int s = bs & (NS - 1);
    float t = s * (1.0f / (NS - 1));
    float g = __ldg(&gamma[h]);
    float sl0 = 2.0f - lane * (1.0f / 32.0f);
    float sl1 = 2.0f - (lane + 32) * (1.0f / 32.0f);
    const float invs = 0.08838834764831845f;
    float a0 = g * t * sl0, a1 = g * t * sl1;
    float b0 = g * (1.0f - t) * sl0, b1 = g * (1.0f - t) * sl1;
    size_t base = ((size_t)bs * NH + h) * NM;
    qt[base + lane]      = cosf(pq0) * invs * expf(a0);
    qt[base + lane + 32] = cosf(pq1) * invs * expf(a1);
    qt[base + lane + 64] = sinf(pq0) * invs * expf(b0);
    qt[base + lane + 96] = sinf(pq1) * invs * expf(b1);
    kt[base + lane]      = cosf(pk0) * invs * expf(-a0);
    kt[base + lane + 32] = cosf(pk1) * invs * expf(-a1);
    kt[base + lane + 64] = sinf(pk0) * invs * expf(-b0);
    kt[base + lane + 96] = sinf(pk1) * invs * expf(-b1);
}

// ---------------- kv = sum_s kt^T v (split over S, deterministic) ----------------
__global__ void kv_partial(const float* __restrict__ kt, const float* __restrict__ v,
                           float* __restrict__ kvp) {
    int bh = blockIdx.x;
    int b = bh >> 3, h = bh & 7;
    int chunk = blockIdx.y;
    int m = threadIdx.x;
    __shared__ float vs[64 * 32];
    float acc[32];
#pragma unroll
    for (int e = 0; e < 32; e++) acc[e] = 0.f;
    int sbase = chunk * (NS / KV_SPLITS);
    for (int s0 = sbase; s0 < sbase + NS / KV_SPLITS; s0 += 64) {
        __syncthreads();
        for (int idx = threadIdx.x; idx < 64 * 32; idx += 128) {
            int i = idx >> 5, e = idx & 31;
            vs[idx] = v[((size_t)(b * NS + s0 + i)) * ND + h * NDH + e];
        }
        __syncthreads();
#pragma unroll 4
        for (int i = 0; i < 64; i++) {
            float kval = kt[(((size_t)(b * NS + s0 + i)) * NH + h) * NM + m];
#pragma unroll
            for (int e = 0; e < 32; e++) acc[e] += kval * vs[i * 32 + e];
        }
    }
    float* dst = kvp + (((size_t)chunk * (NB * NH) + bh) * NM + m) * NDH;
#pragma unroll
    for (int e = 0; e < 32; e++) dst[e] = acc[e];
}

__global__ void kv_reduce(const float* __restrict__ kvp, float* __restrict__ kv) {
    int idx = blockIdx.x * blockDim.x + threadIdx.x;
    if (idx >= NB * NH * NM * NDH) return;
    float s = 0.f;
#pragma unroll
    for (int c = 0; c < KV_SPLITS; c++) s += kvp[(size_t)c * (NB * NH * NM * NDH) + idx];
    kv[idx] = s;
}

// ---------------- o = qt @ kv ----------------
__global__ void attn_o(const float* __restrict__ qt, const float* __restrict__ kv,
                       float* __restrict__ o) {
    int bh = blockIdx.x;
    int b = bh >> 3, h = bh & 7;
    int s0 = blockIdx.y * 32;
    __shared__ float kvs[NM * NDH];
    __shared__ float qsm[32 * NM];
    for (int idx = threadIdx.x; idx < NM * NDH; idx += 256)
        kvs[idx] = kv[(size_t)bh * (NM * NDH) + idx];
    for (int idx = threadIdx.x; idx < 32 * NM; idx += 256) {
        int si = idx >> 7, m = idx & 127;
        qsm[idx] = qt[(((size_t)(b * NS + s0 + si)) * NH + h) * NM + m];
    }
    __syncthreads();
    int e = threadIdx.x & 31, sg = threadIdx.x >> 5;
    float acc[4] = {0.f, 0.f, 0.f, 0.f};
#pragma unroll 4
    for (int m = 0; m < NM; m++) {
        float kval = kvs[m * 32 + e];
#pragma unroll
        for (int i = 0; i < 4; i++) acc[i] += qsm[(sg * 4 + i) * NM + m] * kval;
    }
#pragma unroll
    for (int i = 0; i < 4; i++)
        o[((size_t)(b * NS + s0 + sg * 4 + i)) * ND + h * NDH + e] = acc[i];
}

// ---------------- host launcher ----------------
extern "C" void kernel_launch(void* const* d_in, const int* in_sizes, int n_in,
                              void* d_out, int out_size) {
    const float* x     = (const float*)d_in[0];
    const float* cw0   = (const float*)d_in[1];
    const float* cb0   = (const float*)d_in[2];
    const float* cw1   = (const float*)d_in[3];
    const float* cb1   = (const float*)d_in[4];
    const float* cw2   = (const float*)d_in[5];
    const float* cb2   = (const float*)d_in[6];
    const float* Wq    = (const float*)d_in[7];
    const float* bq    = (const float*)d_in[8];
    const float* Wk    = (const float*)d_in[9];
    const float* bk    = (const float*)d_in[10];
    const float* Wv    = (const float*)d_in[11];
    const float* bv    = (const float*)d_in[12];
    const float* Wo    = (const float*)d_in[13];
    const float* bo    = (const float*)d_in[14];
    const float* omega = (const float*)d_in[15];
    const float* gamma = (const float*)d_in[16];
    const float* W1    = (const float*)d_in[17];
    const float* b1    = (const float*)d_in[18];
    const float* W2    = (const float*)d_in[19];
    const float* b2    = (const float*)d_in[20];
    float* hout = (float*)d_out;

    float *p_h1, *p_h2, *p_ain, *p_q, *p_k, *p_v, *p_qt, *p_kt, *p_kv, *p_kvp, *p_o, *p_mid;
    cudaGetSymbolAddress((void**)&p_h1,  g_h1);
    cudaGetSymbolAddress((void**)&p_h2,  g_h2);
    cudaGetSymbolAddress((void**)&p_ain, g_ain);
    cudaGetSymbolAddress((void**)&p_q,   g_q);
    cudaGetSymbolAddress((void**)&p_k,   g_k);
    cudaGetSymbolAddress((void**)&p_v,   g_v);
    cudaGetSymbolAddress((void**)&p_qt,  g_qt);
    cudaGetSymbolAddress((void**)&p_kt,  g_kt);
    cudaGetSymbolAddress((void**)&p_kv,  g_kv);
    cudaGetSymbolAddress((void**)&p_kvp, g_kvp);
    cudaGetSymbolAddress((void**)&p_o,   g_o);
    cudaGetSymbolAddress((void**)&p_mid, g_mid);

    cudaFuncSetAttribute(gemm_ffma2<false, false>, cudaFuncAttributeMaxDynamicSharedMemorySize, GT_SMEM);
    cudaFuncSetAttribute(gemm_ffma2<false, true>,  cudaFuncAttributeMaxDynamicSharedMemorySize, GT_SMEM);
    cudaFuncSetAttribute(gemm_ffma2<true, false>,  cudaFuncAttributeMaxDynamicSharedMemorySize, GT_SMEM);

    // conv stem
    conv1_pool<<<(NB * NL1 + 255) / 256, 256>>>(x, cw0, cb0, p_h1);
    conv2_pool<<<(NB * NL2 + 255) / 256, 256>>>(p_h1, cw1, cb1, p_h2);
    conv3_pool<<<NB * NS, 256>>>(p_h2, cw2, cb2, hout);

    dim3 gN256(2, NBS / 128);      // N=256
    dim3 gN1024(8, NBS / 128);     // N=1024

    for (int l = 0; l < 2; l++) {
        const float* Wq_l = Wq + (size_t)l * ND * ND;
        const float* Wk_l = Wk + (size_t)l * ND * ND;
        const float* Wv_l = Wv + (size_t)l * ND * ND;
        const float* Wo_l = Wo + (size_t)l * ND * ND;
        const float* W1_l = W1 + (size_t)l * ND * NFF;
        const float* W2_l = W2 + (size_t)l * NFF * ND;
        const float* om_l = omega + (size_t)l * NH * NDH * (NM / 2);
        const float* g_l  = gamma + (size_t)l * NH;

        lc_kernel<<<NBS, ND>>>(hout, p_ain);

        gemm_ffma2<false, false><<<gN256, 256, GT_SMEM>>>(p_ain, Wq_l, bq + l * ND, nullptr, p_q, ND, ND);
        gemm_ffma2<false, false><<<gN256, 256, GT_SMEM>>>(p_ain, Wk_l, bk + l * ND, nullptr, p_k, ND, ND);
        gemm_ffma2<false, false><<<gN256, 256, GT_SMEM>>>(p_ain, Wv_l, bv + l * ND, nullptr, p_v, ND, ND);

        fourier_kernel<<<NBS, 256>>>(p_q, p_k, om_l, g_l, p_qt, p_kt);

        kv_partial<<<dim3(NB * NH, KV_SPLITS), 128>>>(p_kt, p_v, p_kvp);
        kv_reduce<<<(NB * NH * NM * NDH + 255) / 256, 256>>>(p_kvp, p_kv);

        attn_o<<<dim3(NB * NH, NS / 32), 256>>>(p_qt, p_kv, p_o);

        gemm_ffma2<false, true><<<gN256, 256, GT_SMEM>>>(p_o, Wo_l, bo + l * ND, hout, hout, ND, ND);

        lc_kernel<<<NBS, ND>>>(hout, p_ain);

        gemm_ffma2<true, false><<<gN1024, 256, GT_SMEM>>>(p_ain, W1_l, b1 + l * NFF, nullptr, p_mid, NFF, ND);
        gemm_ffma2<false, true><<<gN256, 256, GT_SMEM>>>(p_mid, W2_l, b2 + l * ND, hout, hout, ND, NFF);
    }
}